// round 13
// baseline (speedup 1.0000x reference)
#include <cuda_runtime.h>
#include <cuda_bf16.h>
#include <cstdint>

#define NN 50000
#define EE 850000
#define DIM 256

// ---------------- scratch (device globals; no allocation allowed) -------------
__device__ float g_hp[NN * DIM];                 // GEMM output (fp32)
__device__ __nv_bfloat16 g_ah[NN * DIM];         // A operand hi (x split, then h)
__device__ __nv_bfloat16 g_al[NN * DIM];         // A operand lo
__device__ __nv_bfloat16 g_wh[2 * DIM * DIM];    // W1|W2 hi
__device__ __nv_bfloat16 g_wl[2 * DIM * DIM];    // W1|W2 lo
__device__ float g_ssrc1[NN * 4];
__device__ float g_sdst1[NN * 4];
__device__ float g_ssrc2[NN];
__device__ float g_sdst2[NN];
__device__ float g_alpha[EE * 4];                // per-(edge-slot, head) exp values
__device__ float g_inv  [NN * 4];                // per-(node, head) 1/sum
__device__ int   g_cnt   [NN];
__device__ int   g_rowptr[NN + 1];
__device__ int   g_cursor[NN];
__device__ int   g_srcs  [EE];

// ======================= helpers =============================================
__device__ __forceinline__ uint32_t smem_u32(const void* p) {
    uint32_t a;
    asm("{ .reg .u64 t; cvta.to.shared.u64 t, %1; cvt.u32.u64 %0, t; }" : "=r"(a) : "l"(p));
    return a;
}
#define SW128(b) ((b) ^ (((b) >> 3) & 0x70))

struct Bf4 { uint2 hi, lo; };
__device__ __forceinline__ Bf4 split4(float4 v) {
    Bf4 r;
    __nv_bfloat16 h0 = __float2bfloat16(v.x), h1 = __float2bfloat16(v.y);
    __nv_bfloat16 h2 = __float2bfloat16(v.z), h3 = __float2bfloat16(v.w);
    __nv_bfloat16 l0 = __float2bfloat16(v.x - __bfloat162float(h0));
    __nv_bfloat16 l1 = __float2bfloat16(v.y - __bfloat162float(h1));
    __nv_bfloat16 l2 = __float2bfloat16(v.z - __bfloat162float(h2));
    __nv_bfloat16 l3 = __float2bfloat16(v.w - __bfloat162float(h3));
    r.hi.x = (uint32_t)__bfloat16_as_ushort(h0) | ((uint32_t)__bfloat16_as_ushort(h1) << 16);
    r.hi.y = (uint32_t)__bfloat16_as_ushort(h2) | ((uint32_t)__bfloat16_as_ushort(h3) << 16);
    r.lo.x = (uint32_t)__bfloat16_as_ushort(l0) | ((uint32_t)__bfloat16_as_ushort(l1) << 16);
    r.lo.y = (uint32_t)__bfloat16_as_ushort(l2) | ((uint32_t)__bfloat16_as_ushort(l3) << 16);
    return r;
}

#define LDSM_X4(r0, r1, r2, r3, a) \
    asm volatile("ldmatrix.sync.aligned.m8n8.x4.shared.b16 {%0,%1,%2,%3}, [%4];" \
        : "=r"(r0), "=r"(r1), "=r"(r2), "=r"(r3) : "r"(a))

#define MMA_16816(d, a, b0, b1) \
    asm volatile("mma.sync.aligned.m16n8k16.row.col.f32.bf16.bf16.f32 " \
        "{%0,%1,%2,%3}, {%4,%5,%6,%7}, {%8,%9}, {%0,%1,%2,%3};" \
        : "+f"((d)[0]), "+f"((d)[1]), "+f"((d)[2]), "+f"((d)[3]) \
        : "r"((a)[0]), "r"((a)[1]), "r"((a)[2]), "r"((a)[3]), "r"(b0), "r"(b1))

#define CP16(dst, src, sz) \
    asm volatile("cp.async.cg.shared.global [%0], [%1], 16, %2;" \
        :: "r"(dst), "l"(src), "r"(sz) : "memory")
#define CP_COMMIT() asm volatile("cp.async.commit_group;" ::: "memory")
#define CP_WAIT1() asm volatile("cp.async.wait_group 1;" ::: "memory")
#define CP_WAIT0() asm volatile("cp.async.wait_group 0;" ::: "memory")

// =================== fp32 -> bf16 hi/lo splits ================================
__global__ void split_f4(const float* __restrict__ in, __nv_bfloat16* __restrict__ hi,
                         __nv_bfloat16* __restrict__ lo, int n4) {
    int i = blockIdx.x * blockDim.x + threadIdx.x;
    if (i >= n4) return;
    Bf4 s = split4(((const float4*)in)[i]);
    ((uint2*)hi)[i] = s.hi;
    ((uint2*)lo)[i] = s.lo;
}

__global__ void split_w2(const float* __restrict__ W1, const float* __restrict__ W2,
                         __nv_bfloat16* __restrict__ hi, __nv_bfloat16* __restrict__ lo,
                         int n4w) {
    int i = blockIdx.x * blockDim.x + threadIdx.x;
    if (i >= 2 * n4w) return;
    const float4* src = (i < n4w) ? &((const float4*)W1)[i]
                                  : &((const float4*)W2)[i - n4w];
    Bf4 s = split4(*src);
    ((uint2*)hi)[i] = s.hi;
    ((uint2*)lo)[i] = s.lo;
}

// =================== HMMA bf16 split-3 GEMM + fused attention scores ==========
// CTA tile 128(A rows) x 64(B rows); warp tile 32x32 (4x2 warps); 2 CTAs/SM.
static constexpr int STG = 49152;
static constexpr int SM_GEMM = 2 * STG + 1024;

template <int H>
__global__ __launch_bounds__(256, 2)
void gemm_bf16(const __nv_bfloat16* __restrict__ Ah, const __nv_bfloat16* __restrict__ Al,
               const __nv_bfloat16* __restrict__ Bh, const __nv_bfloat16* __restrict__ Bl,
               float* __restrict__ C, int N,
               const float* __restrict__ a_src, const float* __restrict__ a_dst,
               float* __restrict__ ssrc, float* __restrict__ sdst) {
    extern __shared__ char smem_raw[];
    uint32_t sb0 = smem_u32(smem_raw);
    uint32_t sb  = (sb0 + 1023u) & ~1023u;

    const int tid  = threadIdx.x;
    const int lane = tid & 31;
    const int wid  = tid >> 5;
    const int n0 = blockIdx.x * 128;
    const int m0 = blockIdx.y * 64;
    const int m_warp = (wid >> 1) * 32;
    const int n_warp = (wid & 1) * 32;

    const char* pAh = (const char*)Ah;
    const char* pAl = (const char*)Al;
    const char* pBh = (const char*)Bh;
    const char* pBl = (const char*)Bl;

    auto load_chunk = [&](int c, int b) {
        uint32_t base = sb + b * STG;
#pragma unroll
        for (int i = 0; i < 4; i++) {
            int idx = tid + 256 * i;
            int r   = idx >> 3;
            int k16 = (idx & 7) * 16;
            uint32_t off = SW128((uint32_t)(r * 128 + k16));
            int arow = n0 + r;
            int pa = (arow < N) ? 16 : 0;
            size_t ga = (size_t)min(arow, N - 1) * 512 + (size_t)c * 128 + k16;
            CP16(base + 0     + off, pAh + ga, pa);
            CP16(base + 16384 + off, pAl + ga, pa);
        }
#pragma unroll
        for (int i = 0; i < 2; i++) {
            int idx = tid + 256 * i;
            int r   = idx >> 3;
            int k16 = (idx & 7) * 16;
            uint32_t off = SW128((uint32_t)(r * 128 + k16));
            size_t gb = (size_t)(m0 + r) * 512 + (size_t)c * 128 + k16;
            CP16(base + 32768 + off, pBh + gb, 16);
            CP16(base + 40960 + off, pBl + gb, 16);
        }
        CP_COMMIT();
    };

    float acc[2][4][4];
#pragma unroll
    for (int i = 0; i < 2; i++)
#pragma unroll
        for (int j = 0; j < 4; j++)
#pragma unroll
            for (int q = 0; q < 4; q++) acc[i][j][q] = 0.f;

    const int a_row = (lane & 15);
    const int a_khi = (lane >> 4) << 3;
    const int b_row = (lane & 7) + ((lane >> 4) << 3);
    const int b_khi = ((lane >> 3) & 1) << 3;

    load_chunk(0, 0);

    for (int c = 0; c < 4; c++) {
        if (c < 3) load_chunk(c + 1, (c + 1) & 1);
        if (c < 3) { CP_WAIT1(); } else { CP_WAIT0(); }
        __syncthreads();

        uint32_t base = sb + (c & 1) * STG;
#pragma unroll
        for (int ks = 0; ks < 4; ks++) {
            int kb_a = ks * 16 + a_khi;
            int kb_b = ks * 16 + b_khi;

            uint32_t ah[2][4], al[2][4], bh[2][4], bl[2][4];
#pragma unroll
            for (int mt = 0; mt < 2; mt++) {
                uint32_t off = SW128((uint32_t)((m_warp + mt * 16 + a_row) * 128 + kb_a * 2));
                LDSM_X4(ah[mt][0], ah[mt][1], ah[mt][2], ah[mt][3], base + 0 + off);
                LDSM_X4(al[mt][0], al[mt][1], al[mt][2], al[mt][3], base + 16384 + off);
            }
#pragma unroll
            for (int p = 0; p < 2; p++) {
                uint32_t off = SW128((uint32_t)((n_warp + p * 16 + b_row) * 128 + kb_b * 2));
                LDSM_X4(bh[p][0], bh[p][1], bh[p][2], bh[p][3], base + 32768 + off);
                LDSM_X4(bl[p][0], bl[p][1], bl[p][2], bl[p][3], base + 40960 + off);
            }
#pragma unroll
            for (int mt = 0; mt < 2; mt++)
#pragma unroll
                for (int p = 0; p < 2; p++) {
                    MMA_16816(acc[mt][p * 2 + 0], ah[mt], bh[p][0], bh[p][1]);
                    MMA_16816(acc[mt][p * 2 + 1], ah[mt], bh[p][2], bh[p][3]);
                    MMA_16816(acc[mt][p * 2 + 0], ah[mt], bl[p][0], bl[p][1]);
                    MMA_16816(acc[mt][p * 2 + 1], ah[mt], bl[p][2], bl[p][3]);
                    MMA_16816(acc[mt][p * 2 + 0], al[mt], bh[p][0], bh[p][1]);
                    MMA_16816(acc[mt][p * 2 + 1], al[mt], bh[p][2], bh[p][3]);
                }
        }
        __syncthreads();
    }

    float asv[8], adv[8];
#pragma unroll
    for (int nt = 0; nt < 4; nt++) {
        int col = m0 + n_warp + nt * 8 + (lane & 3) * 2;
        asv[nt * 2 + 0] = a_src[col]; asv[nt * 2 + 1] = a_src[col + 1];
        adv[nt * 2 + 0] = a_dst[col]; adv[nt * 2 + 1] = a_dst[col + 1];
    }

#pragma unroll
    for (int mt = 0; mt < 2; mt++) {
        int rowA = n0 + m_warp + mt * 16 + (lane >> 2);
        float psA = 0.f, pdA = 0.f, psB = 0.f, pdB = 0.f;
#pragma unroll
        for (int nt = 0; nt < 4; nt++) {
            int col = m0 + n_warp + nt * 8 + (lane & 3) * 2;
            if (rowA < N)
                *(float2*)(C + (size_t)rowA * 256 + col)
                    = make_float2(acc[mt][nt][0], acc[mt][nt][1]);
            if (rowA + 8 < N)
                *(float2*)(C + (size_t)(rowA + 8) * 256 + col)
                    = make_float2(acc[mt][nt][2], acc[mt][nt][3]);
            psA += acc[mt][nt][0] * asv[nt * 2] + acc[mt][nt][1] * asv[nt * 2 + 1];
            pdA += acc[mt][nt][0] * adv[nt * 2] + acc[mt][nt][1] * adv[nt * 2 + 1];
            psB += acc[mt][nt][2] * asv[nt * 2] + acc[mt][nt][3] * asv[nt * 2 + 1];
            pdB += acc[mt][nt][2] * adv[nt * 2] + acc[mt][nt][3] * adv[nt * 2 + 1];
        }
#pragma unroll
        for (int o = 1; o <= 2; o <<= 1) {
            psA += __shfl_xor_sync(0xffffffffu, psA, o);
            pdA += __shfl_xor_sync(0xffffffffu, pdA, o);
            psB += __shfl_xor_sync(0xffffffffu, psB, o);
            pdB += __shfl_xor_sync(0xffffffffu, pdB, o);
        }
        if ((lane & 3) == 0) {
            int rowB = rowA + 8;
            if (H == 4) {
                int head = blockIdx.y;
                if (rowA < N) { atomicAdd(&ssrc[(size_t)rowA * 4 + head], psA);
                                atomicAdd(&sdst[(size_t)rowA * 4 + head], pdA); }
                if (rowB < N) { atomicAdd(&ssrc[(size_t)rowB * 4 + head], psB);
                                atomicAdd(&sdst[(size_t)rowB * 4 + head], pdB); }
            } else {
                if (rowA < N) { atomicAdd(&ssrc[rowA], psA); atomicAdd(&sdst[rowA], pdA); }
                if (rowB < N) { atomicAdd(&ssrc[rowB], psB); atomicAdd(&sdst[rowB], pdB); }
            }
        }
    }
}

// =================== CSR build ================================================
__global__ void count_deg(const int* __restrict__ dst, int* __restrict__ cnt, int E) {
    int e = blockIdx.x * blockDim.x + threadIdx.x;
    if (e < E) atomicAdd(&cnt[dst[e]], 1);
}

__global__ void scan_rowptr(const int* __restrict__ cnt, int* __restrict__ rowptr,
                            int* __restrict__ cursor, int N) {
    __shared__ int part[1024];
    int t = threadIdx.x;
    int chunk = (N + 1023) / 1024;
    int b = t * chunk;
    int e = min(b + chunk, N);
    int s = 0;
    for (int i = b; i < e; i++) s += cnt[i];
    part[t] = s;
    __syncthreads();
    for (int off = 1; off < 1024; off <<= 1) {
        int v = (t >= off) ? part[t - off] : 0;
        __syncthreads();
        part[t] += v;
        __syncthreads();
    }
    int run = (t > 0) ? part[t - 1] : 0;
    for (int i = b; i < e; i++) {
        rowptr[i] = run;
        cursor[i] = run;
        run += cnt[i];
    }
    if (t == 1023) rowptr[N] = part[1023];
}

__global__ void scatter_edges(const int* __restrict__ src, const int* __restrict__ dst,
                              int* __restrict__ cursor, int* __restrict__ srcs, int E) {
    int e = blockIdx.x * blockDim.x + threadIdx.x;
    if (e < E) {
        int p = atomicAdd(&cursor[dst[e]], 1);
        srcs[p] = src[e];
    }
}

// =================== softmax alpha (warp per node) — R9 version ===============
template <int H>
__global__ __launch_bounds__(256) void calc_alpha(
    const int* __restrict__ rowptr, const int* __restrict__ srcs,
    const float* __restrict__ ssrc, const float* __restrict__ sdst,
    float* __restrict__ alpha, float* __restrict__ inv, int N) {
    int warp = (blockIdx.x * blockDim.x + threadIdx.x) >> 5;
    int lane = threadIdx.x & 31;
    if (warp >= N) return;
    int n = warp;
    int beg = rowptr[n];
    int deg = rowptr[n + 1] - beg;

    float sd[H];
#pragma unroll
    for (int h = 0; h < H; h++) sd[h] = sdst[(size_t)n * H + h];

    float m[H];
#pragma unroll
    for (int h = 0; h < H; h++) m[h] = -1e30f;
    for (int i = lane; i < deg; i += 32) {
        int s = srcs[beg + i];
#pragma unroll
        for (int h = 0; h < H; h++) {
            float v = ssrc[(size_t)s * H + h] + sd[h];
            v = v > 0.f ? v : 0.2f * v;
            m[h] = fmaxf(m[h], v);
        }
    }
#pragma unroll
    for (int o = 16; o > 0; o >>= 1)
#pragma unroll
        for (int h = 0; h < H; h++)
            m[h] = fmaxf(m[h], __shfl_xor_sync(0xffffffffu, m[h], o));

    float sum[H];
#pragma unroll
    for (int h = 0; h < H; h++) sum[h] = 0.f;
    for (int i = lane; i < deg; i += 32) {
        int s = srcs[beg + i];
        float ex[H];
#pragma unroll
        for (int h = 0; h < H; h++) {
            float v = ssrc[(size_t)s * H + h] + sd[h];
            v = v > 0.f ? v : 0.2f * v;
            ex[h] = __expf(v - m[h]);
            sum[h] += ex[h];
        }
        if (H == 4)
            *(float4*)(alpha + (size_t)(beg + i) * 4)
                = make_float4(ex[0], ex[1], ex[2], ex[3]);
        else
            alpha[beg + i] = ex[0];
    }
#pragma unroll
    for (int o = 16; o > 0; o >>= 1)
#pragma unroll
        for (int h = 0; h < H; h++)
            sum[h] += __shfl_xor_sync(0xffffffffu, sum[h], o);

    if (lane < H) inv[(size_t)n * H + lane] = 1.0f / (sum[lane] + 1e-16f);
}

// =================== SpMM aggregation (smem-staged indices) — R9 version ======
template <int H, bool SPLIT>
__global__ __launch_bounds__(64) void spmm_agg(
    const int* __restrict__ rowptr, const int* __restrict__ srcs,
    const float* __restrict__ alpha, const float* __restrict__ inv,
    const float* __restrict__ hp, float* __restrict__ out,
    __nv_bfloat16* __restrict__ oh, __nv_bfloat16* __restrict__ ol) {
    int n = blockIdx.x;
    int t = threadIdx.x;
    int beg = rowptr[n];
    int deg = rowptr[n + 1] - beg;
    int col = t * 4;
    int h = (H == 1) ? 0 : (t >> 4);

    __shared__ int   sh_s[64];
    __shared__ float sh_a[64 * H];

    float4 acc = make_float4(0.f, 0.f, 0.f, 0.f);

    for (int c0 = 0; c0 < deg; c0 += 64) {
        int cnt = min(64, deg - c0);
        if (t < cnt) {
            sh_s[t] = srcs[beg + c0 + t];
            if (H == 4) {
                float4 a4 = *(const float4*)(alpha + (size_t)(beg + c0 + t) * 4);
                *(float4*)(sh_a + t * 4) = a4;
            } else {
                sh_a[t] = alpha[beg + c0 + t];
            }
        }
        __syncthreads();
        int i = 0;
        for (; i + 2 <= cnt; i += 2) {
            int s0 = sh_s[i];
            int s1 = sh_s[i + 1];
            float a0 = sh_a[i * H + h];
            float a1 = sh_a[(i + 1) * H + h];
            float4 v0 = *(const float4*)(hp + (size_t)s0 * DIM + col);
            float4 v1 = *(const float4*)(hp + (size_t)s1 * DIM + col);
            acc.x += a0 * v0.x + a1 * v1.x;
            acc.y += a0 * v0.y + a1 * v1.y;
            acc.z += a0 * v0.z + a1 * v1.z;
            acc.w += a0 * v0.w + a1 * v1.w;
        }
        if (i < cnt) {
            int s0 = sh_s[i];
            float a0 = sh_a[i * H + h];
            float4 v0 = *(const float4*)(hp + (size_t)s0 * DIM + col);
            acc.x += a0 * v0.x; acc.y += a0 * v0.y;
            acc.z += a0 * v0.z; acc.w += a0 * v0.w;
        }
        __syncthreads();
    }

    float iv = inv[(size_t)n * H + h];
    acc.x *= iv; acc.y *= iv; acc.z *= iv; acc.w *= iv;

    if (SPLIT) {
        acc.x = fmaxf(acc.x, 0.f); acc.y = fmaxf(acc.y, 0.f);
        acc.z = fmaxf(acc.z, 0.f); acc.w = fmaxf(acc.w, 0.f);
        Bf4 s = split4(acc);
        *(uint2*)((char*)oh + ((size_t)n * DIM + col) * 2) = s.hi;
        *(uint2*)((char*)ol + ((size_t)n * DIM + col) * 2) = s.lo;
    } else {
        *(float4*)(out + (size_t)n * DIM + col) = acc;
    }
}

// ==============================================================================
extern "C" void kernel_launch(void* const* d_in, const int* in_sizes, int n_in,
                              void* d_out, int out_size) {
    const float* x      = (const float*)d_in[0];
    const int*   ei     = (const int*)  d_in[1];
    const float* W1     = (const float*)d_in[2];
    const float* a1_src = (const float*)d_in[3];
    const float* a1_dst = (const float*)d_in[4];
    const float* W2     = (const float*)d_in[5];
    const float* a2_src = (const float*)d_in[6];
    const float* a2_dst = (const float*)d_in[7];

    int N = in_sizes[0] / DIM;
    int E = in_sizes[1] / 2;
    const int* src = ei;
    const int* dst = ei + E;

    float *hp, *ssrc1, *sdst1, *ssrc2, *sdst2, *alpha, *inv;
    __nv_bfloat16 *ah, *al, *wh, *wl;
    int *cnt, *rowptr, *cursor, *srcs;
    cudaGetSymbolAddress((void**)&hp,     g_hp);
    cudaGetSymbolAddress((void**)&ah,     g_ah);
    cudaGetSymbolAddress((void**)&al,     g_al);
    cudaGetSymbolAddress((void**)&wh,     g_wh);
    cudaGetSymbolAddress((void**)&wl,     g_wl);
    cudaGetSymbolAddress((void**)&ssrc1,  g_ssrc1);
    cudaGetSymbolAddress((void**)&sdst1,  g_sdst1);
    cudaGetSymbolAddress((void**)&ssrc2,  g_ssrc2);
    cudaGetSymbolAddress((void**)&sdst2,  g_sdst2);
    cudaGetSymbolAddress((void**)&alpha,  g_alpha);
    cudaGetSymbolAddress((void**)&inv,    g_inv);
    cudaGetSymbolAddress((void**)&cnt,    g_cnt);
    cudaGetSymbolAddress((void**)&rowptr, g_rowptr);
    cudaGetSymbolAddress((void**)&cursor, g_cursor);
    cudaGetSymbolAddress((void**)&srcs,   g_srcs);

    float* out = (float*)d_out;
    __nv_bfloat16* wh2 = wh + DIM * DIM;
    __nv_bfloat16* wl2 = wl + DIM * DIM;

    static cudaStream_t s2 = nullptr;
    static cudaEvent_t ev_fork = nullptr, ev_csr = nullptr, ev_w = nullptr;
    if (!s2) {
        cudaStreamCreate(&s2);
        cudaEventCreateWithFlags(&ev_fork, cudaEventDisableTiming);
        cudaEventCreateWithFlags(&ev_csr, cudaEventDisableTiming);
        cudaEventCreateWithFlags(&ev_w, cudaEventDisableTiming);
    }

    cudaFuncSetAttribute(gemm_bf16<4>, cudaFuncAttributeMaxDynamicSharedMemorySize, SM_GEMM);
    cudaFuncSetAttribute(gemm_bf16<1>, cudaFuncAttributeMaxDynamicSharedMemorySize, SM_GEMM);

    dim3 gemm_grid((N + 127) / 128, 4);
    int n4x = N * DIM / 4;
    int n4w = DIM * DIM / 4;
    int nwarp_grid = (N * 32 + 255) / 256;

    // ---- fork: score zeroing + W splits + CSR build on side stream ----
    cudaEventRecord(ev_fork, 0);
    cudaStreamWaitEvent(s2, ev_fork, 0);
    cudaMemsetAsync(ssrc1, 0, (size_t)N * 4 * sizeof(float), s2);
    cudaMemsetAsync(sdst1, 0, (size_t)N * 4 * sizeof(float), s2);
    split_w2<<<(2 * n4w + 127) / 128, 128, 0, s2>>>(W1, W2, wh, wl, n4w);
    cudaEventRecord(ev_w, s2);          // GEMM1 prerequisites on s2 done
    cudaMemsetAsync(cnt, 0, (size_t)N * sizeof(int), s2);
    count_deg<<<(E + 255) / 256, 256, 0, s2>>>(dst, cnt, E);
    scan_rowptr<<<1, 1024, 0, s2>>>(cnt, rowptr, cursor, N);
    scatter_edges<<<(E + 255) / 256, 256, 0, s2>>>(src, dst, cursor, srcs, E);
    cudaMemsetAsync(ssrc2, 0, (size_t)N * sizeof(float), s2);
    cudaMemsetAsync(sdst2, 0, (size_t)N * sizeof(float), s2);
    cudaEventRecord(ev_csr, s2);        // CSR + layer-2 zeroing done

    // ---- main stream: x split + GEMM1 ----
    split_f4<<<(n4x + 127) / 128, 128>>>(x, ah, al, n4x);
    cudaStreamWaitEvent(0, ev_w, 0);
    gemm_bf16<4><<<gemm_grid, 256, SM_GEMM>>>(ah, al, wh, wl, hp, N,
                                              a1_src, a1_dst, ssrc1, sdst1);

    // ---- join CSR, layer-1 softmax + SpMM ----
    cudaStreamWaitEvent(0, ev_csr, 0);
    calc_alpha<4><<<nwarp_grid, 256>>>(rowptr, srcs, ssrc1, sdst1, alpha, inv, N);
    spmm_agg<4, true><<<N, 64>>>(rowptr, srcs, alpha, inv, hp, nullptr, ah, al);

    // ---- layer 2 (H=1) — no mid-chain memsets ----
    gemm_bf16<1><<<gemm_grid, 256, SM_GEMM>>>(ah, al, wh2, wl2, hp, N,
                                              a2_src, a2_dst, ssrc2, sdst2);
    calc_alpha<1><<<nwarp_grid, 256>>>(rowptr, srcs, ssrc2, sdst2, alpha, inv, N);
    spmm_agg<1, false><<<N, 64>>>(rowptr, srcs, alpha, inv, hp, out, nullptr, nullptr);
}

// round 14
// speedup vs baseline: 1.1600x; 1.1600x over previous
#include <cuda_runtime.h>
#include <cuda_bf16.h>
#include <cstdint>

#define NN 50000
#define EE 850000
#define DIM 256

// ---------------- scratch (device globals; no allocation allowed) -------------
__device__ float g_hp[NN * DIM];                 // GEMM output (fp32)
__device__ __nv_bfloat16 g_ah[NN * DIM];         // A operand hi (x split, then h)
__device__ __nv_bfloat16 g_al[NN * DIM];         // A operand lo
__device__ __nv_bfloat16 g_wh[2 * DIM * DIM];    // W1|W2 hi
__device__ __nv_bfloat16 g_wl[2 * DIM * DIM];    // W1|W2 lo
__device__ float g_ssrc[NN * 4];
__device__ float g_sdst[NN * 4];
__device__ float g_alpha[EE * 4];                // per-(edge-slot, head) exp values
__device__ float g_inv  [NN * 4];                // per-(node, head) 1/sum
__device__ int   g_cnt   [NN];
__device__ int   g_rowptr[NN + 1];
__device__ int   g_cursor[NN];
__device__ int   g_srcs  [EE];

// ======================= helpers =============================================
__device__ __forceinline__ uint32_t smem_u32(const void* p) {
    uint32_t a;
    asm("{ .reg .u64 t; cvta.to.shared.u64 t, %1; cvt.u32.u64 %0, t; }" : "=r"(a) : "l"(p));
    return a;
}
#define SW128(b) ((b) ^ (((b) >> 3) & 0x70))

struct Bf4 { uint2 hi, lo; };
__device__ __forceinline__ Bf4 split4(float4 v) {
    Bf4 r;
    __nv_bfloat16 h0 = __float2bfloat16(v.x), h1 = __float2bfloat16(v.y);
    __nv_bfloat16 h2 = __float2bfloat16(v.z), h3 = __float2bfloat16(v.w);
    __nv_bfloat16 l0 = __float2bfloat16(v.x - __bfloat162float(h0));
    __nv_bfloat16 l1 = __float2bfloat16(v.y - __bfloat162float(h1));
    __nv_bfloat16 l2 = __float2bfloat16(v.z - __bfloat162float(h2));
    __nv_bfloat16 l3 = __float2bfloat16(v.w - __bfloat162float(h3));
    r.hi.x = (uint32_t)__bfloat16_as_ushort(h0) | ((uint32_t)__bfloat16_as_ushort(h1) << 16);
    r.hi.y = (uint32_t)__bfloat16_as_ushort(h2) | ((uint32_t)__bfloat16_as_ushort(h3) << 16);
    r.lo.x = (uint32_t)__bfloat16_as_ushort(l0) | ((uint32_t)__bfloat16_as_ushort(l1) << 16);
    r.lo.y = (uint32_t)__bfloat16_as_ushort(l2) | ((uint32_t)__bfloat16_as_ushort(l3) << 16);
    return r;
}

#define LDSM_X4(r0, r1, r2, r3, a) \
    asm volatile("ldmatrix.sync.aligned.m8n8.x4.shared.b16 {%0,%1,%2,%3}, [%4];" \
        : "=r"(r0), "=r"(r1), "=r"(r2), "=r"(r3) : "r"(a))

#define MMA_16816(d, a, b0, b1) \
    asm volatile("mma.sync.aligned.m16n8k16.row.col.f32.bf16.bf16.f32 " \
        "{%0,%1,%2,%3}, {%4,%5,%6,%7}, {%8,%9}, {%0,%1,%2,%3};" \
        : "+f"((d)[0]), "+f"((d)[1]), "+f"((d)[2]), "+f"((d)[3]) \
        : "r"((a)[0]), "r"((a)[1]), "r"((a)[2]), "r"((a)[3]), "r"(b0), "r"(b1))

#define CP16(dst, src, sz) \
    asm volatile("cp.async.cg.shared.global [%0], [%1], 16, %2;" \
        :: "r"(dst), "l"(src), "r"(sz) : "memory")
#define CP_COMMIT() asm volatile("cp.async.commit_group;" ::: "memory")
#define CP_WAIT1() asm volatile("cp.async.wait_group 1;" ::: "memory")
#define CP_WAIT0() asm volatile("cp.async.wait_group 0;" ::: "memory")

// =================== fp32 -> bf16 hi/lo splits ================================
__global__ void split_f4(const float* __restrict__ in, __nv_bfloat16* __restrict__ hi,
                         __nv_bfloat16* __restrict__ lo, int n4) {
    int i = blockIdx.x * blockDim.x + threadIdx.x;
    if (i >= n4) return;
    Bf4 s = split4(((const float4*)in)[i]);
    ((uint2*)hi)[i] = s.hi;
    ((uint2*)lo)[i] = s.lo;
}

__global__ void split_w2(const float* __restrict__ W1, const float* __restrict__ W2,
                         __nv_bfloat16* __restrict__ hi, __nv_bfloat16* __restrict__ lo,
                         int n4w) {
    int i = blockIdx.x * blockDim.x + threadIdx.x;
    if (i >= 2 * n4w) return;
    const float4* src = (i < n4w) ? &((const float4*)W1)[i]
                                  : &((const float4*)W2)[i - n4w];
    Bf4 s = split4(*src);
    ((uint2*)hi)[i] = s.hi;
    ((uint2*)lo)[i] = s.lo;
}

// =================== HMMA bf16 split-3 GEMM + fused attention scores ==========
// CTA tile 128(A rows) x 64(B rows); warp tile 32x32 (4x2 warps); 2 CTAs/SM.
static constexpr int STG = 49152;
static constexpr int SM_GEMM = 2 * STG + 1024;

template <int H>
__global__ __launch_bounds__(256, 2)
void gemm_bf16(const __nv_bfloat16* __restrict__ Ah, const __nv_bfloat16* __restrict__ Al,
               const __nv_bfloat16* __restrict__ Bh, const __nv_bfloat16* __restrict__ Bl,
               float* __restrict__ C, int N,
               const float* __restrict__ a_src, const float* __restrict__ a_dst,
               float* __restrict__ ssrc, float* __restrict__ sdst) {
    extern __shared__ char smem_raw[];
    uint32_t sb0 = smem_u32(smem_raw);
    uint32_t sb  = (sb0 + 1023u) & ~1023u;

    const int tid  = threadIdx.x;
    const int lane = tid & 31;
    const int wid  = tid >> 5;
    const int n0 = blockIdx.x * 128;          // A row block
    const int m0 = blockIdx.y * 64;           // B row (output col) block
    const int m_warp = (wid >> 1) * 32;
    const int n_warp = (wid & 1) * 32;

    const char* pAh = (const char*)Ah;
    const char* pAl = (const char*)Al;
    const char* pBh = (const char*)Bh;
    const char* pBl = (const char*)Bl;

    auto load_chunk = [&](int c, int b) {
        uint32_t base = sb + b * STG;
#pragma unroll
        for (int i = 0; i < 4; i++) {               // A: 1024 16B ops
            int idx = tid + 256 * i;
            int r   = idx >> 3;
            int k16 = (idx & 7) * 16;
            uint32_t off = SW128((uint32_t)(r * 128 + k16));
            int arow = n0 + r;
            int pa = (arow < N) ? 16 : 0;
            size_t ga = (size_t)min(arow, N - 1) * 512 + (size_t)c * 128 + k16;
            CP16(base + 0     + off, pAh + ga, pa);
            CP16(base + 16384 + off, pAl + ga, pa);
        }
#pragma unroll
        for (int i = 0; i < 2; i++) {               // B: 512 16B ops
            int idx = tid + 256 * i;
            int r   = idx >> 3;
            int k16 = (idx & 7) * 16;
            uint32_t off = SW128((uint32_t)(r * 128 + k16));
            size_t gb = (size_t)(m0 + r) * 512 + (size_t)c * 128 + k16;
            CP16(base + 32768 + off, pBh + gb, 16);
            CP16(base + 40960 + off, pBl + gb, 16);
        }
        CP_COMMIT();
    };

    float acc[2][4][4];
#pragma unroll
    for (int i = 0; i < 2; i++)
#pragma unroll
        for (int j = 0; j < 4; j++)
#pragma unroll
            for (int q = 0; q < 4; q++) acc[i][j][q] = 0.f;

    const int a_row = (lane & 15);
    const int a_khi = (lane >> 4) << 3;
    const int b_row = (lane & 7) + ((lane >> 4) << 3);
    const int b_khi = ((lane >> 3) & 1) << 3;

    load_chunk(0, 0);

    for (int c = 0; c < 4; c++) {
        if (c < 3) load_chunk(c + 1, (c + 1) & 1);
        if (c < 3) { CP_WAIT1(); } else { CP_WAIT0(); }
        __syncthreads();

        uint32_t base = sb + (c & 1) * STG;
#pragma unroll
        for (int ks = 0; ks < 4; ks++) {
            int kb_a = ks * 16 + a_khi;
            int kb_b = ks * 16 + b_khi;

            uint32_t ah[2][4], al[2][4], bh[2][4], bl[2][4];
#pragma unroll
            for (int mt = 0; mt < 2; mt++) {
                uint32_t off = SW128((uint32_t)((m_warp + mt * 16 + a_row) * 128 + kb_a * 2));
                LDSM_X4(ah[mt][0], ah[mt][1], ah[mt][2], ah[mt][3], base + 0 + off);
                LDSM_X4(al[mt][0], al[mt][1], al[mt][2], al[mt][3], base + 16384 + off);
            }
#pragma unroll
            for (int p = 0; p < 2; p++) {
                uint32_t off = SW128((uint32_t)((n_warp + p * 16 + b_row) * 128 + kb_b * 2));
                LDSM_X4(bh[p][0], bh[p][1], bh[p][2], bh[p][3], base + 32768 + off);
                LDSM_X4(bl[p][0], bl[p][1], bl[p][2], bl[p][3], base + 40960 + off);
            }
#pragma unroll
            for (int mt = 0; mt < 2; mt++)
#pragma unroll
                for (int p = 0; p < 2; p++) {
                    MMA_16816(acc[mt][p * 2 + 0], ah[mt], bh[p][0], bh[p][1]);
                    MMA_16816(acc[mt][p * 2 + 1], ah[mt], bh[p][2], bh[p][3]);
                    MMA_16816(acc[mt][p * 2 + 0], ah[mt], bl[p][0], bl[p][1]);
                    MMA_16816(acc[mt][p * 2 + 1], ah[mt], bl[p][2], bl[p][3]);
                    MMA_16816(acc[mt][p * 2 + 0], al[mt], bh[p][0], bh[p][1]);
                    MMA_16816(acc[mt][p * 2 + 1], al[mt], bh[p][2], bh[p][3]);
                }
        }
        __syncthreads();
    }

    // ---- epilogue: C stores + fused per-head score partials (atomicAdd) ----
    float asv[8], adv[8];
#pragma unroll
    for (int nt = 0; nt < 4; nt++) {
        int col = m0 + n_warp + nt * 8 + (lane & 3) * 2;
        asv[nt * 2 + 0] = a_src[col]; asv[nt * 2 + 1] = a_src[col + 1];
        adv[nt * 2 + 0] = a_dst[col]; adv[nt * 2 + 1] = a_dst[col + 1];
    }

#pragma unroll
    for (int mt = 0; mt < 2; mt++) {
        int rowA = n0 + m_warp + mt * 16 + (lane >> 2);
        float psA = 0.f, pdA = 0.f, psB = 0.f, pdB = 0.f;
#pragma unroll
        for (int nt = 0; nt < 4; nt++) {
            int col = m0 + n_warp + nt * 8 + (lane & 3) * 2;
            if (rowA < N)
                *(float2*)(C + (size_t)rowA * 256 + col)
                    = make_float2(acc[mt][nt][0], acc[mt][nt][1]);
            if (rowA + 8 < N)
                *(float2*)(C + (size_t)(rowA + 8) * 256 + col)
                    = make_float2(acc[mt][nt][2], acc[mt][nt][3]);
            psA += acc[mt][nt][0] * asv[nt * 2] + acc[mt][nt][1] * asv[nt * 2 + 1];
            pdA += acc[mt][nt][0] * adv[nt * 2] + acc[mt][nt][1] * adv[nt * 2 + 1];
            psB += acc[mt][nt][2] * asv[nt * 2] + acc[mt][nt][3] * asv[nt * 2 + 1];
            pdB += acc[mt][nt][2] * adv[nt * 2] + acc[mt][nt][3] * adv[nt * 2 + 1];
        }
#pragma unroll
        for (int o = 1; o <= 2; o <<= 1) {
            psA += __shfl_xor_sync(0xffffffffu, psA, o);
            pdA += __shfl_xor_sync(0xffffffffu, pdA, o);
            psB += __shfl_xor_sync(0xffffffffu, psB, o);
            pdB += __shfl_xor_sync(0xffffffffu, pdB, o);
        }
        if ((lane & 3) == 0) {
            int rowB = rowA + 8;
            if (H == 4) {
                int head = blockIdx.y;     // 64 cols per head, 64-col CTA tile
                if (rowA < N) { atomicAdd(&ssrc[(size_t)rowA * 4 + head], psA);
                                atomicAdd(&sdst[(size_t)rowA * 4 + head], pdA); }
                if (rowB < N) { atomicAdd(&ssrc[(size_t)rowB * 4 + head], psB);
                                atomicAdd(&sdst[(size_t)rowB * 4 + head], pdB); }
            } else {
                if (rowA < N) { atomicAdd(&ssrc[rowA], psA); atomicAdd(&sdst[rowA], pdA); }
                if (rowB < N) { atomicAdd(&ssrc[rowB], psB); atomicAdd(&sdst[rowB], pdB); }
            }
        }
    }
}

// =================== CSR build ================================================
__global__ void count_deg(const int* __restrict__ dst, int* __restrict__ cnt, int E) {
    int e = blockIdx.x * blockDim.x + threadIdx.x;
    if (e < E) atomicAdd(&cnt[dst[e]], 1);
}

__global__ void scan_rowptr(const int* __restrict__ cnt, int* __restrict__ rowptr,
                            int* __restrict__ cursor, int N) {
    __shared__ int part[1024];
    int t = threadIdx.x;
    int chunk = (N + 1023) / 1024;
    int b = t * chunk;
    int e = min(b + chunk, N);
    int s = 0;
    for (int i = b; i < e; i++) s += cnt[i];
    part[t] = s;
    __syncthreads();
    for (int off = 1; off < 1024; off <<= 1) {
        int v = (t >= off) ? part[t - off] : 0;
        __syncthreads();
        part[t] += v;
        __syncthreads();
    }
    int run = (t > 0) ? part[t - 1] : 0;
    for (int i = b; i < e; i++) {
        rowptr[i] = run;
        cursor[i] = run;
        run += cnt[i];
    }
    if (t == 1023) rowptr[N] = part[1023];
}

__global__ void scatter_edges(const int* __restrict__ src, const int* __restrict__ dst,
                              int* __restrict__ cursor, int* __restrict__ srcs, int E) {
    int e = blockIdx.x * blockDim.x + threadIdx.x;
    if (e < E) {
        int p = atomicAdd(&cursor[dst[e]], 1);
        srcs[p] = src[e];
    }
}

// =================== softmax alpha (warp per node) ============================
template <int H>
__global__ __launch_bounds__(256) void calc_alpha(
    const int* __restrict__ rowptr, const int* __restrict__ srcs,
    const float* __restrict__ ssrc, const float* __restrict__ sdst,
    float* __restrict__ alpha, float* __restrict__ inv, int N) {
    int warp = (blockIdx.x * blockDim.x + threadIdx.x) >> 5;
    int lane = threadIdx.x & 31;
    if (warp >= N) return;
    int n = warp;
    int beg = rowptr[n];
    int deg = rowptr[n + 1] - beg;

    float sd[H];
#pragma unroll
    for (int h = 0; h < H; h++) sd[h] = sdst[(size_t)n * H + h];

    float m[H];
#pragma unroll
    for (int h = 0; h < H; h++) m[h] = -1e30f;
    for (int i = lane; i < deg; i += 32) {
        int s = srcs[beg + i];
#pragma unroll
        for (int h = 0; h < H; h++) {
            float v = ssrc[(size_t)s * H + h] + sd[h];
            v = v > 0.f ? v : 0.2f * v;
            m[h] = fmaxf(m[h], v);
        }
    }
#pragma unroll
    for (int o = 16; o > 0; o >>= 1)
#pragma unroll
        for (int h = 0; h < H; h++)
            m[h] = fmaxf(m[h], __shfl_xor_sync(0xffffffffu, m[h], o));

    float sum[H];
#pragma unroll
    for (int h = 0; h < H; h++) sum[h] = 0.f;
    for (int i = lane; i < deg; i += 32) {
        int s = srcs[beg + i];
        float ex[H];
#pragma unroll
        for (int h = 0; h < H; h++) {
            float v = ssrc[(size_t)s * H + h] + sd[h];
            v = v > 0.f ? v : 0.2f * v;
            ex[h] = __expf(v - m[h]);
            sum[h] += ex[h];
        }
        if (H == 4)
            *(float4*)(alpha + (size_t)(beg + i) * 4)
                = make_float4(ex[0], ex[1], ex[2], ex[3]);
        else
            alpha[beg + i] = ex[0];
    }
#pragma unroll
    for (int o = 16; o > 0; o >>= 1)
#pragma unroll
        for (int h = 0; h < H; h++)
            sum[h] += __shfl_xor_sync(0xffffffffu, sum[h], o);

    if (lane < H) inv[(size_t)n * H + lane] = 1.0f / (sum[lane] + 1e-16f);
}

// =================== SpMM aggregation (smem-staged indices) ====================
template <int H, bool SPLIT>
__global__ __launch_bounds__(64) void spmm_agg(
    const int* __restrict__ rowptr, const int* __restrict__ srcs,
    const float* __restrict__ alpha, const float* __restrict__ inv,
    const float* __restrict__ hp, float* __restrict__ out,
    __nv_bfloat16* __restrict__ oh, __nv_bfloat16* __restrict__ ol) {
    int n = blockIdx.x;
    int t = threadIdx.x;
    int beg = rowptr[n];
    int deg = rowptr[n + 1] - beg;
    int col = t * 4;
    int h = (H == 1) ? 0 : (t >> 4);

    __shared__ int   sh_s[64];
    __shared__ float sh_a[64 * H];

    float4 acc = make_float4(0.f, 0.f, 0.f, 0.f);

    for (int c0 = 0; c0 < deg; c0 += 64) {
        int cnt = min(64, deg - c0);
        if (t < cnt) {
            sh_s[t] = srcs[beg + c0 + t];
            if (H == 4) {
                float4 a4 = *(const float4*)(alpha + (size_t)(beg + c0 + t) * 4);
                *(float4*)(sh_a + t * 4) = a4;
            } else {
                sh_a[t] = alpha[beg + c0 + t];
            }
        }
        __syncthreads();
        int i = 0;
        for (; i + 2 <= cnt; i += 2) {
            int s0 = sh_s[i];
            int s1 = sh_s[i + 1];
            float a0 = sh_a[i * H + h];
            float a1 = sh_a[(i + 1) * H + h];
            float4 v0 = *(const float4*)(hp + (size_t)s0 * DIM + col);
            float4 v1 = *(const float4*)(hp + (size_t)s1 * DIM + col);
            acc.x += a0 * v0.x + a1 * v1.x;
            acc.y += a0 * v0.y + a1 * v1.y;
            acc.z += a0 * v0.z + a1 * v1.z;
            acc.w += a0 * v0.w + a1 * v1.w;
        }
        if (i < cnt) {
            int s0 = sh_s[i];
            float a0 = sh_a[i * H + h];
            float4 v0 = *(const float4*)(hp + (size_t)s0 * DIM + col);
            acc.x += a0 * v0.x; acc.y += a0 * v0.y;
            acc.z += a0 * v0.z; acc.w += a0 * v0.w;
        }
        __syncthreads();
    }

    float iv = inv[(size_t)n * H + h];
    acc.x *= iv; acc.y *= iv; acc.z *= iv; acc.w *= iv;

    if (SPLIT) {
        acc.x = fmaxf(acc.x, 0.f); acc.y = fmaxf(acc.y, 0.f);
        acc.z = fmaxf(acc.z, 0.f); acc.w = fmaxf(acc.w, 0.f);
        Bf4 s = split4(acc);
        *(uint2*)((char*)oh + ((size_t)n * DIM + col) * 2) = s.hi;
        *(uint2*)((char*)ol + ((size_t)n * DIM + col) * 2) = s.lo;
    } else {
        *(float4*)(out + (size_t)n * DIM + col) = acc;
    }
}

// ==============================================================================
extern "C" void kernel_launch(void* const* d_in, const int* in_sizes, int n_in,
                              void* d_out, int out_size) {
    const float* x      = (const float*)d_in[0];
    const int*   ei     = (const int*)  d_in[1];
    const float* W1     = (const float*)d_in[2];
    const float* a1_src = (const float*)d_in[3];
    const float* a1_dst = (const float*)d_in[4];
    const float* W2     = (const float*)d_in[5];
    const float* a2_src = (const float*)d_in[6];
    const float* a2_dst = (const float*)d_in[7];

    int N = in_sizes[0] / DIM;
    int E = in_sizes[1] / 2;
    const int* src = ei;
    const int* dst = ei + E;

    float *hp, *ssrc, *sdst, *alpha, *inv;
    __nv_bfloat16 *ah, *al, *wh, *wl;
    int *cnt, *rowptr, *cursor, *srcs;
    cudaGetSymbolAddress((void**)&hp,     g_hp);
    cudaGetSymbolAddress((void**)&ah,     g_ah);
    cudaGetSymbolAddress((void**)&al,     g_al);
    cudaGetSymbolAddress((void**)&wh,     g_wh);
    cudaGetSymbolAddress((void**)&wl,     g_wl);
    cudaGetSymbolAddress((void**)&ssrc,   g_ssrc);
    cudaGetSymbolAddress((void**)&sdst,   g_sdst);
    cudaGetSymbolAddress((void**)&alpha,  g_alpha);
    cudaGetSymbolAddress((void**)&inv,    g_inv);
    cudaGetSymbolAddress((void**)&cnt,    g_cnt);
    cudaGetSymbolAddress((void**)&rowptr, g_rowptr);
    cudaGetSymbolAddress((void**)&cursor, g_cursor);
    cudaGetSymbolAddress((void**)&srcs,   g_srcs);

    float* out = (float*)d_out;
    __nv_bfloat16* wh2 = wh + DIM * DIM;
    __nv_bfloat16* wl2 = wl + DIM * DIM;

    static cudaStream_t s2 = nullptr;
    static cudaEvent_t ev_fork = nullptr, ev_csr = nullptr;
    if (!s2) {
        cudaStreamCreate(&s2);
        cudaEventCreateWithFlags(&ev_fork, cudaEventDisableTiming);
        cudaEventCreateWithFlags(&ev_csr, cudaEventDisableTiming);
    }

    cudaFuncSetAttribute(gemm_bf16<4>, cudaFuncAttributeMaxDynamicSharedMemorySize, SM_GEMM);
    cudaFuncSetAttribute(gemm_bf16<1>, cudaFuncAttributeMaxDynamicSharedMemorySize, SM_GEMM);

    dim3 gemm_grid((N + 127) / 128, 4);
    int n4x = N * DIM / 4;
    int n4w = DIM * DIM / 4;
    int nwarp_grid = (N * 32 + 255) / 256;

    // ---- fork: CSR build on side stream ----
    cudaEventRecord(ev_fork, 0);
    cudaStreamWaitEvent(s2, ev_fork, 0);
    cudaMemsetAsync(cnt, 0, (size_t)N * sizeof(int), s2);
    count_deg<<<(E + 255) / 256, 256, 0, s2>>>(dst, cnt, E);
    scan_rowptr<<<1, 1024, 0, s2>>>(cnt, rowptr, cursor, N);
    scatter_edges<<<(E + 255) / 256, 256, 0, s2>>>(src, dst, cursor, srcs, E);
    cudaEventRecord(ev_csr, s2);

    // ---- main stream: splits + zero scores + GEMM1 ----
    split_w2<<<(2 * n4w + 127) / 128, 128>>>(W1, W2, wh, wl, n4w);
    split_f4<<<(n4x + 127) / 128, 128>>>(x, ah, al, n4x);
    cudaMemsetAsync(ssrc, 0, (size_t)N * 4 * sizeof(float));
    cudaMemsetAsync(sdst, 0, (size_t)N * 4 * sizeof(float));
    gemm_bf16<4><<<gemm_grid, 256, SM_GEMM>>>(ah, al, wh, wl, hp, N,
                                              a1_src, a1_dst, ssrc, sdst);

    // ---- join CSR, layer-1 softmax + SpMM ----
    cudaStreamWaitEvent(0, ev_csr, 0);
    calc_alpha<4><<<nwarp_grid, 256>>>(rowptr, srcs, ssrc, sdst, alpha, inv, N);
    spmm_agg<4, true><<<N, 64>>>(rowptr, srcs, alpha, inv, hp, nullptr, ah, al);

    // ---- layer 2 (H=1) ----
    cudaMemsetAsync(ssrc, 0, (size_t)N * sizeof(float));
    cudaMemsetAsync(sdst, 0, (size_t)N * sizeof(float));
    gemm_bf16<1><<<gemm_grid, 256, SM_GEMM>>>(ah, al, wh2, wl2, hp, N,
                                              a2_src, a2_dst, ssrc, sdst);
    calc_alpha<1><<<nwarp_grid, 256>>>(rowptr, srcs, ssrc, sdst, alpha, inv, N);
    spmm_agg<1, false><<<N, 64>>>(rowptr, srcs, alpha, inv, hp, out, nullptr, nullptr);
}